// round 15
// baseline (speedup 1.0000x reference)
#include <cuda_runtime.h>
#include <cfloat>
#include <cstdint>

#define B_ 2
#define N_ 8192
#define M_ 4096
#define C_ 64
#define HID_ 256
#define KNN_ 15
#define P_ (B_*N_)

// ---------------- scratch (no allocations allowed) ----------------
__device__ float4 g_pc4[B_*M_];           // (x,y,z,|c|^2) per clean point
__device__ float  g_R[(size_t)P_*HID_];   // 16 MB: weighted relu sums
__device__ float  g_DF[(size_t)P_*128];   // 8 MB : [close_feat | co_feat]
__device__ float  g_sw[P_];               // sum of weights per point
__device__ unsigned long long g_ckey[P_]; // packed (dist,idx) argmin key
__device__ int    g_knn[B_*M_*KNN_];      // 15-NN (self excluded) per clean point
__device__ float  g_w2as[HID_*6];         // BN-folded W2a
__device__ float  g_b2as[HID_];
__device__ float  g_w1hi[384*C_];         // tf32-hi of fused stage-1 B matrix [k][o]
__device__ float  g_w1lo[384*C_];         // tf32-lo residual
__device__ float  g_bb2[C_];              // b2b . W1a'[:,128:192]
__device__ float  g_b1as[C_];
__device__ float  g_w1bT[C_*C_];          // W1b transposed [k][o]

__device__ __forceinline__ float tf32_hi(float a) {
    uint32_t u;
    asm("cvt.rna.tf32.f32 %0, %1;" : "=r"(u) : "f"(a));
    return __uint_as_float(u);
}

__device__ __forceinline__ void mma_tf32(float* d, uint32_t a0, uint32_t a1,
                                         uint32_t a2, uint32_t a3,
                                         uint32_t b0, uint32_t b1) {
    asm volatile("mma.sync.aligned.m16n8k8.row.col.f32.tf32.tf32.f32 "
                 "{%0,%1,%2,%3}, {%4,%5,%6,%7}, {%8,%9}, {%0,%1,%2,%3};\n"
                 : "+f"(d[0]), "+f"(d[1]), "+f"(d[2]), "+f"(d[3])
                 : "r"(a0), "r"(a1), "r"(a2), "r"(a3), "r"(b0), "r"(b1));
}

// ---------------- weight prep: fold BN scale, transpose ----------------
__global__ void k_prep(const float* __restrict__ w2a, const float* __restrict__ b2a,
                       const float* __restrict__ g2a, const float* __restrict__ bt2a,
                       const float* __restrict__ b1a, const float* __restrict__ g1a,
                       const float* __restrict__ bt1a, const float* __restrict__ w1b) {
    int t = threadIdx.x;
    const float sc = rsqrtf(1.0f + 1e-5f);
    if (blockIdx.x == 0) {
        if (t < HID_) {
            float s = g2a[t] * sc;
            #pragma unroll
            for (int d = 0; d < 6; d++) g_w2as[t*6+d] = w2a[t*6+d] * s;
            g_b2as[t] = b2a[t] * s + bt2a[t];
        }
        if (t < C_) {
            float s = g1a[t] * sc;
            g_b1as[t] = b1a[t] * s + bt1a[t];
        }
    } else {
        int i = (blockIdx.x - 1) * 256 + t;            // 16 blocks cover 4096
        if (i < C_*C_) { int j = i >> 6, o = i & 63; g_w1bT[i] = w1b[o*C_+j]; }
    }
}

// W' fold, coalesced + tf32 hi/lo split.
__global__ void __launch_bounds__(256) k_prepw(const float* __restrict__ w2b,
                                               const float* __restrict__ w1a,
                                               const float* __restrict__ g1a,
                                               const float* __restrict__ b2b) {
    __shared__ float wa[C_];
    int o = blockIdx.x;                     // 64 blocks
    int h = threadIdx.x;                    // 256 threads
    float s = g1a[o] * rsqrtf(1.0f + 1e-5f);
    if (h < C_) wa[h] = w1a[o*192 + 128 + h];
    if (h < 128) {
        float v = w1a[o*192 + h] * s;
        float hi = tf32_hi(v);
        g_w1hi[h*C_ + o] = hi;
        g_w1lo[h*C_ + o] = tf32_hi(v - hi);
    }
    __syncthreads();
    float acc = 0.f;
    #pragma unroll 8
    for (int o2 = 0; o2 < C_; o2++)
        acc = fmaf(__ldg(&w2b[o2*HID_ + h]), wa[o2], acc);   // coalesced across h
    float v = acc * s;
    float hi = tf32_hi(v);
    g_w1hi[(128 + h)*C_ + o] = hi;
    g_w1lo[(128 + h)*C_ + o] = tf32_hi(v - hi);
    if (h == 0) {
        float a = 0.f;
        for (int o2 = 0; o2 < C_; o2++) a = fmaf(b2b[o2], wa[o2], a);
        g_bb2[o] = a * s;
    }
}

// ---------------- pc4 + ckey init (no weight dependency) ----------------
__global__ void k_pc4(const float* __restrict__ pcl) {
    int idx = blockIdx.x * 256 + threadIdx.x;          // 16384 threads
    if (idx < B_*M_) {
        float x = pcl[idx*3], y = pcl[idx*3+1], z = pcl[idx*3+2];
        g_pc4[idx] = make_float4(x, y, z, fmaf(x,x, fmaf(y,y, z*z)));
    }
    if (idx < P_) g_ckey[idx] = 0xFFFFFFFFFFFFFFFFull;
}

// ---------------- nearest clean point: 4 queries/thread, fine-grained grid ----
#define CLQ_ 4
__global__ void __launch_bounds__(256) k_close(const float* __restrict__ noise) {
    int qg = blockIdx.x >> 6;                  // 16 query groups of 1024
    int ms = blockIdx.x & 63;                  // 64 M-chunks of 64
    int p0 = qg * 1024 + threadIdx.x * CLQ_;
    int b  = p0 >> 13;
    const float4* PC = g_pc4 + b*M_;
    float qx[CLQ_], qy[CLQ_], qz[CLQ_], bd[CLQ_];
    int bi[CLQ_];
    #pragma unroll
    for (int q = 0; q < CLQ_; q++) {
        const float* np = noise + (size_t)(p0+q)*3;
        qx[q] = -2.f*np[0]; qy[q] = -2.f*np[1]; qz[q] = -2.f*np[2];
        bd[q] = FLT_MAX; bi[q] = 0;
    }
    int c0 = ms * 64;
    #pragma unroll 8
    for (int i = 0; i < 64; i++) {
        float4 c = __ldg(&PC[c0 + i]);
        #pragma unroll
        for (int q = 0; q < CLQ_; q++) {
            float d = fmaf(c.x, qx[q], fmaf(c.y, qy[q], fmaf(c.z, qz[q], c.w)));
            if (d < bd[q]) { bd[q] = d; bi[q] = c0 + i; }
        }
    }
    #pragma unroll
    for (int q = 0; q < CLQ_; q++) {
        unsigned u = __float_as_uint(bd[q]);
        u = (u & 0x80000000u) ? ~u : (u | 0x80000000u);   // order-preserving map
        unsigned long long key = ((unsigned long long)u << 32) | (unsigned)bi[q];
        atomicMin(&g_ckey[p0+q], key);
    }
}

// ---------------- 15-NN per clean point: warp-cooperative distributed top-K ----
__global__ void __launch_bounds__(512) k_knn() {
    extern __shared__ float4 sc[];                // 64 KB: whole batch cloud
    int blk  = blockIdx.x;                        // 512 blocks: 256/batch, 16 pts each
    int b    = blk >> 8;
    int w    = threadIdx.x >> 5;
    int lane = threadIdx.x & 31;
    int m    = (blk & 255) * 16 + w;
    const float4* PC = g_pc4 + b*M_;
    for (int i = threadIdx.x; i < M_; i += 512) sc[i] = PC[i];
    __syncthreads();
    float4 qc = sc[m];
    float qx = -2.f*qc.x, qy = -2.f*qc.y, qz = -2.f*qc.z;
    float Dl = FLT_MAX;                           // list entry held by this lane
    int   Il = -1;
    float worst = FLT_MAX;                        // warp-uniform 15th best
    for (int t0 = 0; t0 < M_; t0 += 32) {
        int c = t0 + lane;
        float4 cc = sc[c];
        float d = fmaf(cc.x, qx, fmaf(cc.y, qy, fmaf(cc.z, qz, cc.w)));
        bool pass = (d < worst) & (c != m);
        unsigned mask = __ballot_sync(0xffffffffu, pass);
        while (mask) {                            // warp-uniform loop
            int s = __ffs(mask) - 1;
            mask &= mask - 1;
            float bd = __shfl_sync(0xffffffffu, d, s);
            int   bix = t0 + s;
            if (bd < worst) {                     // warp-uniform condition
                float pd = __shfl_up_sync(0xffffffffu, Dl, 1);
                int   pi = __shfl_up_sync(0xffffffffu, Il, 1);
                if (lane == 0) { pd = -FLT_MAX; pi = -1; }
                if (lane < KNN_ && Dl >= bd) {
                    if (pd >= bd) { Dl = pd; Il = pi; }
                    else          { Dl = bd; Il = bix; }
                }
                worst = __shfl_sync(0xffffffffu, Dl, KNN_ - 1);
            }
        }
    }
    if (lane < KNN_) g_knn[(b*M_+m)*KNN_ + lane] = Il;
}

// ---------------- assemble: v computed on the fly (no g_v gather) -------------
__global__ void __launch_bounds__(256) k_assemble(const float* __restrict__ noise,
                                                  const float* __restrict__ feature) {
    int w = threadIdx.x >> 5, lane = threadIdx.x & 31;
    int p = blockIdx.x * 8 + w;           // warp per noisy point
    int b = p >> 13;                      // N = 8192
    int m0 = (int)(g_ckey[p] & 0xFFFFFFFFull);
    const float4* PC = g_pc4 + b*M_;
    const float* FB = feature + b*M_*C_;
    float nx = noise[p*3], ny = noise[p*3+1], nz = noise[p*3+2];
    float4 cp = PC[m0];
    float w0[8], w1[8], w2[8], t[8], r[8];
    #pragma unroll
    for (int j = 0; j < 8; j++) {
        int c = lane + 32*j;
        const float* wv = g_w2as + c*6;
        w0[j] = wv[0]; w1[j] = wv[1]; w2[j] = wv[2];
        t[j] = g_b2as[c] + wv[3]*cp.x + wv[4]*cp.y + wv[5]*cp.z
                         - (w0[j]*nx + w1[j]*ny + w2[j]*nz);
        r[j] = 0.f;
    }
    float S = 0.f, co0 = 0.f, co1 = 0.f;
    const int* nbp = g_knn + (b*M_+m0)*KNN_;
    #pragma unroll 1
    for (int k = 0; k < KNN_; k++) {
        int nb = nbp[k];
        float4 cc = PC[nb];                           // one broadcast LDG.128
        float dx = cc.x-nx, dy = cc.y-ny, dz = cc.z-nz;
        float dst = sqrtf(fmaf(dx, dx, fmaf(dy, dy, dz*dz)));
        float e = __expf(-10.f * dst);
        S += e;
        #pragma unroll
        for (int j = 0; j < 8; j++) {
            float h = fmaf(w0[j], cc.x, fmaf(w1[j], cc.y, fmaf(w2[j], cc.z, t[j])));
            r[j] = fmaf(e, fmaxf(h, 0.f), r[j]);
        }
        co0 = fmaf(e, FB[nb*C_+lane],    co0);
        co1 = fmaf(e, FB[nb*C_+32+lane], co1);
    }
    float inv = 1.f / (S + 1e-7f);
    float* Rr = g_R + (size_t)p*HID_;
    #pragma unroll
    for (int j = 0; j < 8; j++) Rr[lane + 32*j] = r[j] * inv;
    float* dfp = g_DF + (size_t)p*128;
    dfp[lane]       = FB[m0*C_+lane];
    dfp[32+lane]    = FB[m0*C_+32+lane];
    dfp[64+lane]    = co0 * inv;
    dfp[96+lane]    = co1 * inv;
    if (lane == 0) g_sw[p] = S * inv;
}

// ---------------- fused GEMM, tf32 MMA stage1 + FFMA stage2 -------------------
#define GS_AS   0
#define GS_BH   (128*20)
#define GS_BL   (GS_BH + 16*72)
#define GS_H1   (GS_BL + 16*72)
#define GS_SW   (GS_H1 + 64*136)
#define GS_B1   (GS_SW + 128)
#define GS_B2   (GS_B1 + 64)
#define GS_TOT  ((GS_B2 + 64) * 4)

__global__ void __launch_bounds__(256) k_gemm(const float* __restrict__ b1b,
                                              float* __restrict__ out) {
    extern __shared__ float sm[];
    float* As  = sm + GS_AS;
    float* Bh  = sm + GS_BH;
    float* Bl  = sm + GS_BL;
    float* H1T = sm + GS_H1;
    float* sws = sm + GS_SW;
    float* sb1 = sm + GS_B1;
    float* sb2 = sm + GS_B2;
    int tid = threadIdx.x;
    int p0 = blockIdx.x * 128;
    int wid = tid >> 5, lane = tid & 31;
    int lp = tid >> 1, kh = (tid & 1) * 8;
    int grp = lane >> 2, tig = lane & 3;

    if (tid < 128) sws[tid] = g_sw[p0 + tid];
    if (tid < 64)  { sb1[tid] = g_b1as[tid]; sb2[tid] = g_bb2[tid]; }

    float acc[32];
    #pragma unroll
    for (int i = 0; i < 32; i++) acc[i] = 0.f;

    for (int k0 = 0; k0 < 384; k0 += 16) {
        const float* ap = (k0 < 128)
            ? g_DF + (size_t)(p0+lp)*128 + k0 + kh
            : g_R  + (size_t)(p0+lp)*HID_ + (k0 - 128) + kh;
        *(float4*)&As[lp*20 + kh]     = *(const float4*)ap;
        *(float4*)&As[lp*20 + kh + 4] = *(const float4*)(ap + 4);
        int bk = tid >> 4, bn = (tid & 15) * 4;
        *(float4*)&Bh[bk*72 + bn] = *(const float4*)(g_w1hi + (k0+bk)*C_ + bn);
        *(float4*)&Bl[bk*72 + bn] = *(const float4*)(g_w1lo + (k0+bk)*C_ + bn);
        __syncthreads();
        #pragma unroll
        for (int ks = 0; ks < 16; ks += 8) {
            int r0 = wid*16 + grp, c0 = ks + tig;
            float af0 = As[r0*20 + c0];
            float af1 = As[(r0+8)*20 + c0];
            float af2 = As[r0*20 + c0 + 4];
            float af3 = As[(r0+8)*20 + c0 + 4];
            float h0 = tf32_hi(af0), h1 = tf32_hi(af1), h2 = tf32_hi(af2), h3 = tf32_hi(af3);
            uint32_t ah0 = __float_as_uint(h0), ah1 = __float_as_uint(h1);
            uint32_t ah2 = __float_as_uint(h2), ah3 = __float_as_uint(h3);
            uint32_t al0 = __float_as_uint(tf32_hi(af0 - h0));
            uint32_t al1 = __float_as_uint(tf32_hi(af1 - h1));
            uint32_t al2 = __float_as_uint(tf32_hi(af2 - h2));
            uint32_t al3 = __float_as_uint(tf32_hi(af3 - h3));
            #pragma unroll
            for (int nt = 0; nt < 8; nt++) {
                int bidx = (ks + tig)*72 + nt*8 + grp;
                uint32_t bh0 = __float_as_uint(Bh[bidx]);
                uint32_t bh1 = __float_as_uint(Bh[bidx + 4*72]);
                uint32_t bl0 = __float_as_uint(Bl[bidx]);
                uint32_t bl1 = __float_as_uint(Bl[bidx + 4*72]);
                float* d = acc + nt*4;
                mma_tf32(d, ah0, ah1, ah2, ah3, bh0, bh1);
                mma_tf32(d, ah0, ah1, ah2, ah3, bl0, bl1);
                mma_tf32(d, al0, al1, al2, al3, bh0, bh1);
            }
        }
        __syncthreads();
    }
    {
        int row = wid*16 + grp;
        float sw0 = sws[row], sw1 = sws[row+8];
        #pragma unroll
        for (int nt = 0; nt < 8; nt++) {
            int col = nt*8 + tig*2;
            float b0v = sb1[col],   c0v = sb2[col];
            float b1v = sb1[col+1], c1v = sb2[col+1];
            float* d = acc + nt*4;
            H1T[col*136 + row]       = fmaxf(d[0] + b0v + sw0*c0v, 0.f);
            H1T[(col+1)*136 + row]   = fmaxf(d[1] + b1v + sw0*c1v, 0.f);
            H1T[col*136 + row + 8]   = fmaxf(d[2] + b0v + sw1*c0v, 0.f);
            H1T[(col+1)*136 + row+8] = fmaxf(d[3] + b1v + sw1*c1v, 0.f);
        }
    }
    __syncthreads();
    int ty = tid >> 4, tx = tid & 15;
    float acc2[8][4];
    #pragma unroll
    for (int i = 0; i < 8; i++)
        #pragma unroll
        for (int j = 0; j < 4; j++) acc2[i][j] = 0.f;
    #pragma unroll 8
    for (int kc = 0; kc < 64; kc++) {
        float4 A0 = *(const float4*)&H1T[kc*136 + ty*8];
        float4 A1 = *(const float4*)&H1T[kc*136 + ty*8 + 4];
        float4 Bv = *(const float4*)(g_w1bT + kc*C_ + tx*4);
        float a[8] = {A0.x,A0.y,A0.z,A0.w,A1.x,A1.y,A1.z,A1.w};
        float bb[4] = {Bv.x,Bv.y,Bv.z,Bv.w};
        #pragma unroll
        for (int i = 0; i < 8; i++)
            #pragma unroll
            for (int j = 0; j < 4; j++)
                acc2[i][j] = fmaf(a[i], bb[j], acc2[i][j]);
    }
    #pragma unroll
    for (int i = 0; i < 8; i++) {
        float* dst = out + (size_t)(p0 + ty*8 + i)*C_ + tx*4;
        #pragma unroll
        for (int j = 0; j < 4; j++) dst[j] = acc2[i][j] + b1b[tx*4+j];
    }
}

// ---------------- launch ----------------
extern "C" void kernel_launch(void* const* d_in, const int* in_sizes, int n_in,
                              void* d_out, int out_size) {
    const float* pcl     = (const float*)d_in[0];
    const float* noise   = (const float*)d_in[1];
    const float* feature = (const float*)d_in[2];
    const float* w2a  = (const float*)d_in[3];
    const float* b2a  = (const float*)d_in[4];
    const float* g2a  = (const float*)d_in[5];
    const float* bt2a = (const float*)d_in[6];
    const float* w2b  = (const float*)d_in[7];
    const float* b2b  = (const float*)d_in[8];
    const float* w1a  = (const float*)d_in[9];
    const float* b1a  = (const float*)d_in[10];
    const float* g1a  = (const float*)d_in[11];
    const float* bt1a = (const float*)d_in[12];
    const float* w1b  = (const float*)d_in[13];
    const float* b1b  = (const float*)d_in[14];
    float* out = (float*)d_out;

    // one-time infra (first call is the non-captured correctness run)
    static cudaStream_t s1 = 0, s2 = 0;
    static cudaEvent_t  e0 = 0, e1 = 0, e2 = 0, e3 = 0;
    static bool infra_ok = false;
    static bool tried = false;
    if (!tried) {
        tried = true;
        infra_ok = (cudaStreamCreateWithFlags(&s1, cudaStreamNonBlocking) == cudaSuccess)
                && (cudaStreamCreateWithFlags(&s2, cudaStreamNonBlocking) == cudaSuccess)
                && (cudaEventCreateWithFlags(&e0, cudaEventDisableTiming) == cudaSuccess)
                && (cudaEventCreateWithFlags(&e1, cudaEventDisableTiming) == cudaSuccess)
                && (cudaEventCreateWithFlags(&e2, cudaEventDisableTiming) == cudaSuccess)
                && (cudaEventCreateWithFlags(&e3, cudaEventDisableTiming) == cudaSuccess);
        cudaFuncSetAttribute(k_knn, cudaFuncAttributeMaxDynamicSharedMemorySize, M_*16);
        cudaFuncSetAttribute(k_gemm, cudaFuncAttributeMaxDynamicSharedMemorySize, GS_TOT);
    }

    if (infra_ok) {
        // s2: prep + prepw (weights; needed by assemble/gemm, not by close/knn)
        cudaEventRecord(e0, 0);
        cudaStreamWaitEvent(s2, e0, 0);
        k_prep<<<17, 256, 0, s2>>>(w2a, b2a, g2a, bt2a, b1a, g1a, bt1a, w1b);
        k_prepw<<<64, 256, 0, s2>>>(w2b, w1a, g1a, b2b);
        // s0: pc4, then fork knn to s1
        k_pc4<<<64, 256>>>(pcl);
        cudaEventRecord(e1, 0);
        cudaStreamWaitEvent(s1, e1, 0);
        k_knn<<<512, 512, M_*16, s1>>>();
        // s0 leg: close
        k_close<<<1024, 256>>>(noise);
        // join knn + weights before assemble
        cudaEventRecord(e2, s1);
        cudaStreamWaitEvent(0, e2, 0);
        cudaEventRecord(e3, s2);
        cudaStreamWaitEvent(0, e3, 0);
        k_assemble<<<2048, 256>>>(noise, feature);
        k_gemm<<<128, 256, GS_TOT>>>(b1b, out);
    } else {
        k_prep<<<17, 256>>>(w2a, b2a, g2a, bt2a, b1a, g1a, bt1a, w1b);
        k_prepw<<<64, 256>>>(w2b, w1a, g1a, b2b);
        k_pc4<<<64, 256>>>(pcl);
        k_knn<<<512, 512, M_*16>>>();
        k_close<<<1024, 256>>>(noise);
        k_assemble<<<2048, 256>>>(noise, feature);
        k_gemm<<<128, 256, GS_TOT>>>(b1b, out);
    }
}

// round 16
// speedup vs baseline: 1.5709x; 1.5709x over previous
#include <cuda_runtime.h>
#include <cfloat>
#include <cstdint>

#define B_ 2
#define N_ 8192
#define M_ 4096
#define C_ 64
#define HID_ 256
#define KNN_ 15
#define P_ (B_*N_)

// ---------------- scratch (no allocations allowed) ----------------
__device__ float  g_v[B_*M_*HID_];        // 8 MB : W2a'[:, :3] . pcl[m]
__device__ float4 g_pc4[B_*M_];           // (x,y,z,|c|^2) per clean point
__device__ float  g_R[(size_t)P_*HID_];   // 16 MB: weighted relu sums
__device__ float  g_DF[(size_t)P_*128];   // 8 MB : [close_feat | co_feat]
__device__ float  g_sw[P_];               // sum of weights per point
__device__ unsigned long long g_ckey[P_]; // packed (dist,idx) argmin key
__device__ int    g_knn[B_*M_*KNN_];      // 15-NN (self excluded) per clean point
__device__ float  g_w2as[HID_*6];         // BN-folded W2a
__device__ float  g_b2as[HID_];
__device__ float  g_w1hi[384*C_];         // tf32-hi of fused stage-1 B matrix [k][o]
__device__ float  g_w1lo[384*C_];         // tf32-lo residual
__device__ float  g_bb2[C_];              // b2b . W1a'[:,128:192]
__device__ float  g_b1as[C_];
__device__ float  g_w1bT[C_*C_];          // W1b transposed [k][o]

__device__ __forceinline__ float tf32_hi(float a) {
    uint32_t u;
    asm("cvt.rna.tf32.f32 %0, %1;" : "=r"(u) : "f"(a));
    return __uint_as_float(u);
}

__device__ __forceinline__ void mma_tf32(float* d, uint32_t a0, uint32_t a1,
                                         uint32_t a2, uint32_t a3,
                                         uint32_t b0, uint32_t b1) {
    asm volatile("mma.sync.aligned.m16n8k8.row.col.f32.tf32.tf32.f32 "
                 "{%0,%1,%2,%3}, {%4,%5,%6,%7}, {%8,%9}, {%0,%1,%2,%3};\n"
                 : "+f"(d[0]), "+f"(d[1]), "+f"(d[2]), "+f"(d[3])
                 : "r"(a0), "r"(a1), "r"(a2), "r"(a3), "r"(b0), "r"(b1));
}

// ---------------- weight prep: fold BN scale, transpose ----------------
__global__ void k_prep(const float* __restrict__ w2a, const float* __restrict__ b2a,
                       const float* __restrict__ g2a, const float* __restrict__ bt2a,
                       const float* __restrict__ b1a, const float* __restrict__ g1a,
                       const float* __restrict__ bt1a, const float* __restrict__ w1b) {
    int t = threadIdx.x;
    const float sc = rsqrtf(1.0f + 1e-5f);
    if (blockIdx.x == 0) {
        if (t < HID_) {
            float s = g2a[t] * sc;
            #pragma unroll
            for (int d = 0; d < 6; d++) g_w2as[t*6+d] = w2a[t*6+d] * s;
            g_b2as[t] = b2a[t] * s + bt2a[t];
        }
        if (t < C_) {
            float s = g1a[t] * sc;
            g_b1as[t] = b1a[t] * s + bt1a[t];
        }
    } else {
        int i = (blockIdx.x - 1) * 256 + t;            // 16 blocks cover 4096
        if (i < C_*C_) { int j = i >> 6, o = i & 63; g_w1bT[i] = w1b[o*C_+j]; }
    }
}

// W' fold, coalesced + tf32 hi/lo split.
__global__ void __launch_bounds__(256) k_prepw(const float* __restrict__ w2b,
                                               const float* __restrict__ w1a,
                                               const float* __restrict__ g1a,
                                               const float* __restrict__ b2b) {
    __shared__ float wa[C_];
    int o = blockIdx.x;                     // 64 blocks
    int h = threadIdx.x;                    // 256 threads
    float s = g1a[o] * rsqrtf(1.0f + 1e-5f);
    if (h < C_) wa[h] = w1a[o*192 + 128 + h];
    if (h < 128) {
        float v = w1a[o*192 + h] * s;
        float hi = tf32_hi(v);
        g_w1hi[h*C_ + o] = hi;
        g_w1lo[h*C_ + o] = tf32_hi(v - hi);
    }
    __syncthreads();
    float acc = 0.f;
    #pragma unroll 8
    for (int o2 = 0; o2 < C_; o2++)
        acc = fmaf(__ldg(&w2b[o2*HID_ + h]), wa[o2], acc);   // coalesced across h
    float v = acc * s;
    float hi = tf32_hi(v);
    g_w1hi[(128 + h)*C_ + o] = hi;
    g_w1lo[(128 + h)*C_ + o] = tf32_hi(v - hi);
    if (h == 0) {
        float a = 0.f;
        for (int o2 = 0; o2 < C_; o2++) a = fmaf(b2b[o2], wa[o2], a);
        g_bb2[o] = a * s;
    }
}

// ---------------- pc4 + ckey init (no weight dependency) ----------------
__global__ void k_pc4(const float* __restrict__ pcl) {
    int idx = blockIdx.x * 256 + threadIdx.x;          // 16384 threads
    if (idx < B_*M_) {
        float x = pcl[idx*3], y = pcl[idx*3+1], z = pcl[idx*3+2];
        g_pc4[idx] = make_float4(x, y, z, fmaf(x,x, fmaf(y,y, z*z)));
    }
    if (idx < P_) g_ckey[idx] = 0xFFFFFFFFFFFFFFFFull;
}

// ---------------- v table (needs g_w2as) ----------------
__global__ void k_vtab(const float* __restrict__ pcl) {
    int idx = blockIdx.x * blockDim.x + threadIdx.x;   // B*M*HID threads
    if (idx >= B_*M_*HID_) return;
    int pm = idx >> 8, c = idx & 255;
    float x = pcl[pm*3], y = pcl[pm*3+1], z = pcl[pm*3+2];
    g_v[idx] = g_w2as[c*6]*x + g_w2as[c*6+1]*y + g_w2as[c*6+2]*z;
}

// ---------------- nearest clean point: 4 queries/thread, fine-grained grid ----
#define CLQ_ 4
__global__ void __launch_bounds__(256) k_close(const float* __restrict__ noise) {
    int qg = blockIdx.x >> 6;                  // 16 query groups of 1024
    int ms = blockIdx.x & 63;                  // 64 M-chunks of 64
    int p0 = qg * 1024 + threadIdx.x * CLQ_;
    int b  = p0 >> 13;
    const float4* PC = g_pc4 + b*M_;
    float qx[CLQ_], qy[CLQ_], qz[CLQ_], bd[CLQ_];
    int bi[CLQ_];
    #pragma unroll
    for (int q = 0; q < CLQ_; q++) {
        const float* np = noise + (size_t)(p0+q)*3;
        qx[q] = -2.f*np[0]; qy[q] = -2.f*np[1]; qz[q] = -2.f*np[2];
        bd[q] = FLT_MAX; bi[q] = 0;
    }
    int c0 = ms * 64;
    #pragma unroll 8
    for (int i = 0; i < 64; i++) {
        float4 c = __ldg(&PC[c0 + i]);
        #pragma unroll
        for (int q = 0; q < CLQ_; q++) {
            float d = fmaf(c.x, qx[q], fmaf(c.y, qy[q], fmaf(c.z, qz[q], c.w)));
            if (d < bd[q]) { bd[q] = d; bi[q] = c0 + i; }
        }
    }
    #pragma unroll
    for (int q = 0; q < CLQ_; q++) {
        unsigned u = __float_as_uint(bd[q]);
        u = (u & 0x80000000u) ? ~u : (u | 0x80000000u);   // order-preserving map
        unsigned long long key = ((unsigned long long)u << 32) | (unsigned)bi[q];
        atomicMin(&g_ckey[p0+q], key);
    }
}

// ---------------- 15-NN per clean point: warp-cooperative distributed top-K ----
// No smem staging (cloud is L1/L2 resident); 256-thread blocks -> one wave.
// Insert path: worst refreshed once per non-empty batch; stale passes are no-ops.
__global__ void __launch_bounds__(256) k_knn() {
    int blk  = blockIdx.x;                        // 1024 blocks: 512/batch, 8 pts each
    int b    = blk >> 9;
    int w    = threadIdx.x >> 5;
    int lane = threadIdx.x & 31;
    int m    = (blk & 511) * 8 + w;
    const float4* __restrict__ PC = g_pc4 + (size_t)b*M_;
    float4 qc = __ldg(&PC[m]);
    float qx = -2.f*qc.x, qy = -2.f*qc.y, qz = -2.f*qc.z;
    float Dl = FLT_MAX;                           // list entry held by this lane
    int   Il = -1;
    float worst = FLT_MAX;                        // refreshed per non-empty batch
    for (int t0 = 0; t0 < M_; t0 += 32) {
        int c = t0 + lane;
        float4 cc = __ldg(&PC[c]);
        float d = fmaf(cc.x, qx, fmaf(cc.y, qy, fmaf(cc.z, qz, cc.w)));
        bool pass = (d < worst) & (c != m);
        unsigned mask = __ballot_sync(0xffffffffu, pass);
        if (mask) {
            do {
                int s = __ffs(mask) - 1;
                mask &= mask - 1;
                float bd = __shfl_sync(0xffffffffu, d, s);
                int   bix = t0 + s;
                float pd = __shfl_up_sync(0xffffffffu, Dl, 1);
                int   pi = __shfl_up_sync(0xffffffffu, Il, 1);
                if (lane == 0) { pd = -FLT_MAX; pi = -1; }
                if (lane < KNN_ && Dl >= bd) {    // no-op if bd >= current worst
                    if (pd >= bd) { Dl = pd; Il = pi; }
                    else          { Dl = bd; Il = bix; }
                }
            } while (mask);
            worst = __shfl_sync(0xffffffffu, Dl, KNN_ - 1);
        }
    }
    if (lane < KNN_) g_knn[((size_t)b*M_+m)*KNN_ + lane] = Il;
}

// ---------------- assemble: weights, weighted relu sums R, df[0:128] ----------------
__global__ void __launch_bounds__(256) k_assemble(const float* __restrict__ pcl,
                                                  const float* __restrict__ noise,
                                                  const float* __restrict__ feature) {
    int w = threadIdx.x >> 5, lane = threadIdx.x & 31;
    int p = blockIdx.x * 8 + w;           // warp per noisy point
    int b = p >> 13;                      // N = 8192
    int m0 = (int)(g_ckey[p] & 0xFFFFFFFFull);
    const float* PB = pcl + b*M_*3;
    const float* FB = feature + b*M_*C_;
    float nx = noise[p*3], ny = noise[p*3+1], nz = noise[p*3+2];
    float cx = PB[m0*3], cy = PB[m0*3+1], cz = PB[m0*3+2];
    float t[8], r[8];
    #pragma unroll
    for (int j = 0; j < 8; j++) {
        int c = lane + 32*j;
        const float* wv = g_w2as + c*6;
        t[j] = g_b2as[c] + wv[3]*cx + wv[4]*cy + wv[5]*cz
                         - (wv[0]*nx + wv[1]*ny + wv[2]*nz);
        r[j] = 0.f;
    }
    float S = 0.f, co0 = 0.f, co1 = 0.f;
    const int* nbp = g_knn + (b*M_+m0)*KNN_;
    #pragma unroll 1
    for (int k = 0; k < KNN_; k++) {
        int nb = nbp[k];
        float dx = PB[nb*3]-nx, dy = PB[nb*3+1]-ny, dz = PB[nb*3+2]-nz;
        float dst = sqrtf(fmaf(dx, dx, fmaf(dy, dy, dz*dz)));
        float e = __expf(-10.f * dst);
        S += e;
        const float* vr = g_v + (nb + b*M_)*HID_;
        #pragma unroll
        for (int j = 0; j < 8; j++) {
            float h = vr[lane + 32*j] + t[j];
            r[j] = fmaf(e, fmaxf(h, 0.f), r[j]);
        }
        co0 = fmaf(e, FB[nb*C_+lane],    co0);
        co1 = fmaf(e, FB[nb*C_+32+lane], co1);
    }
    float inv = 1.f / (S + 1e-7f);
    float* Rr = g_R + (size_t)p*HID_;
    #pragma unroll
    for (int j = 0; j < 8; j++) Rr[lane + 32*j] = r[j] * inv;
    float* dfp = g_DF + (size_t)p*128;
    dfp[lane]       = FB[m0*C_+lane];
    dfp[32+lane]    = FB[m0*C_+32+lane];
    dfp[64+lane]    = co0 * inv;
    dfp[96+lane]    = co1 * inv;
    if (lane == 0) g_sw[p] = S * inv;
}

// ---------------- fused GEMM, tf32 MMA stage1 + FFMA stage2 -------------------
#define GS_AS   0
#define GS_BH   (128*20)
#define GS_BL   (GS_BH + 16*72)
#define GS_H1   (GS_BL + 16*72)
#define GS_SW   (GS_H1 + 64*136)
#define GS_B1   (GS_SW + 128)
#define GS_B2   (GS_B1 + 64)
#define GS_TOT  ((GS_B2 + 64) * 4)

__global__ void __launch_bounds__(256) k_gemm(const float* __restrict__ b1b,
                                              float* __restrict__ out) {
    extern __shared__ float sm[];
    float* As  = sm + GS_AS;
    float* Bh  = sm + GS_BH;
    float* Bl  = sm + GS_BL;
    float* H1T = sm + GS_H1;
    float* sws = sm + GS_SW;
    float* sb1 = sm + GS_B1;
    float* sb2 = sm + GS_B2;
    int tid = threadIdx.x;
    int p0 = blockIdx.x * 128;
    int wid = tid >> 5, lane = tid & 31;
    int lp = tid >> 1, kh = (tid & 1) * 8;
    int grp = lane >> 2, tig = lane & 3;

    if (tid < 128) sws[tid] = g_sw[p0 + tid];
    if (tid < 64)  { sb1[tid] = g_b1as[tid]; sb2[tid] = g_bb2[tid]; }

    float acc[32];
    #pragma unroll
    for (int i = 0; i < 32; i++) acc[i] = 0.f;

    for (int k0 = 0; k0 < 384; k0 += 16) {
        const float* ap = (k0 < 128)
            ? g_DF + (size_t)(p0+lp)*128 + k0 + kh
            : g_R  + (size_t)(p0+lp)*HID_ + (k0 - 128) + kh;
        *(float4*)&As[lp*20 + kh]     = *(const float4*)ap;
        *(float4*)&As[lp*20 + kh + 4] = *(const float4*)(ap + 4);
        int bk = tid >> 4, bn = (tid & 15) * 4;
        *(float4*)&Bh[bk*72 + bn] = *(const float4*)(g_w1hi + (k0+bk)*C_ + bn);
        *(float4*)&Bl[bk*72 + bn] = *(const float4*)(g_w1lo + (k0+bk)*C_ + bn);
        __syncthreads();
        #pragma unroll
        for (int ks = 0; ks < 16; ks += 8) {
            int r0 = wid*16 + grp, c0 = ks + tig;
            float af0 = As[r0*20 + c0];
            float af1 = As[(r0+8)*20 + c0];
            float af2 = As[r0*20 + c0 + 4];
            float af3 = As[(r0+8)*20 + c0 + 4];
            float h0 = tf32_hi(af0), h1 = tf32_hi(af1), h2 = tf32_hi(af2), h3 = tf32_hi(af3);
            uint32_t ah0 = __float_as_uint(h0), ah1 = __float_as_uint(h1);
            uint32_t ah2 = __float_as_uint(h2), ah3 = __float_as_uint(h3);
            uint32_t al0 = __float_as_uint(tf32_hi(af0 - h0));
            uint32_t al1 = __float_as_uint(tf32_hi(af1 - h1));
            uint32_t al2 = __float_as_uint(tf32_hi(af2 - h2));
            uint32_t al3 = __float_as_uint(tf32_hi(af3 - h3));
            #pragma unroll
            for (int nt = 0; nt < 8; nt++) {
                int bidx = (ks + tig)*72 + nt*8 + grp;
                uint32_t bh0 = __float_as_uint(Bh[bidx]);
                uint32_t bh1 = __float_as_uint(Bh[bidx + 4*72]);
                uint32_t bl0 = __float_as_uint(Bl[bidx]);
                uint32_t bl1 = __float_as_uint(Bl[bidx + 4*72]);
                float* d = acc + nt*4;
                mma_tf32(d, ah0, ah1, ah2, ah3, bh0, bh1);
                mma_tf32(d, ah0, ah1, ah2, ah3, bl0, bl1);
                mma_tf32(d, al0, al1, al2, al3, bh0, bh1);
            }
        }
        __syncthreads();
    }
    {
        int row = wid*16 + grp;
        float sw0 = sws[row], sw1 = sws[row+8];
        #pragma unroll
        for (int nt = 0; nt < 8; nt++) {
            int col = nt*8 + tig*2;
            float b0v = sb1[col],   c0v = sb2[col];
            float b1v = sb1[col+1], c1v = sb2[col+1];
            float* d = acc + nt*4;
            H1T[col*136 + row]       = fmaxf(d[0] + b0v + sw0*c0v, 0.f);
            H1T[(col+1)*136 + row]   = fmaxf(d[1] + b1v + sw0*c1v, 0.f);
            H1T[col*136 + row + 8]   = fmaxf(d[2] + b0v + sw1*c0v, 0.f);
            H1T[(col+1)*136 + row+8] = fmaxf(d[3] + b1v + sw1*c1v, 0.f);
        }
    }
    __syncthreads();
    int ty = tid >> 4, tx = tid & 15;
    float acc2[8][4];
    #pragma unroll
    for (int i = 0; i < 8; i++)
        #pragma unroll
        for (int j = 0; j < 4; j++) acc2[i][j] = 0.f;
    #pragma unroll 8
    for (int kc = 0; kc < 64; kc++) {
        float4 A0 = *(const float4*)&H1T[kc*136 + ty*8];
        float4 A1 = *(const float4*)&H1T[kc*136 + ty*8 + 4];
        float4 Bv = *(const float4*)(g_w1bT + kc*C_ + tx*4);
        float a[8] = {A0.x,A0.y,A0.z,A0.w,A1.x,A1.y,A1.z,A1.w};
        float bb[4] = {Bv.x,Bv.y,Bv.z,Bv.w};
        #pragma unroll
        for (int i = 0; i < 8; i++)
            #pragma unroll
            for (int j = 0; j < 4; j++)
                acc2[i][j] = fmaf(a[i], bb[j], acc2[i][j]);
    }
    #pragma unroll
    for (int i = 0; i < 8; i++) {
        float* dst = out + (size_t)(p0 + ty*8 + i)*C_ + tx*4;
        #pragma unroll
        for (int j = 0; j < 4; j++) dst[j] = acc2[i][j] + b1b[tx*4+j];
    }
}

// ---------------- launch ----------------
extern "C" void kernel_launch(void* const* d_in, const int* in_sizes, int n_in,
                              void* d_out, int out_size) {
    const float* pcl     = (const float*)d_in[0];
    const float* noise   = (const float*)d_in[1];
    const float* feature = (const float*)d_in[2];
    const float* w2a  = (const float*)d_in[3];
    const float* b2a  = (const float*)d_in[4];
    const float* g2a  = (const float*)d_in[5];
    const float* bt2a = (const float*)d_in[6];
    const float* w2b  = (const float*)d_in[7];
    const float* b2b  = (const float*)d_in[8];
    const float* w1a  = (const float*)d_in[9];
    const float* b1a  = (const float*)d_in[10];
    const float* g1a  = (const float*)d_in[11];
    const float* bt1a = (const float*)d_in[12];
    const float* w1b  = (const float*)d_in[13];
    const float* b1b  = (const float*)d_in[14];
    float* out = (float*)d_out;

    // one-time infra (first call is the non-captured correctness run)
    static cudaStream_t s1 = 0, s2 = 0;
    static cudaEvent_t  e0 = 0, e1 = 0, e2 = 0, e3 = 0;
    static bool infra_ok = false;
    static bool tried = false;
    if (!tried) {
        tried = true;
        infra_ok = (cudaStreamCreateWithFlags(&s1, cudaStreamNonBlocking) == cudaSuccess)
                && (cudaStreamCreateWithFlags(&s2, cudaStreamNonBlocking) == cudaSuccess)
                && (cudaEventCreateWithFlags(&e0, cudaEventDisableTiming) == cudaSuccess)
                && (cudaEventCreateWithFlags(&e1, cudaEventDisableTiming) == cudaSuccess)
                && (cudaEventCreateWithFlags(&e2, cudaEventDisableTiming) == cudaSuccess)
                && (cudaEventCreateWithFlags(&e3, cudaEventDisableTiming) == cudaSuccess);
        cudaFuncSetAttribute(k_gemm, cudaFuncAttributeMaxDynamicSharedMemorySize, GS_TOT);
    }

    if (infra_ok) {
        // s2: prepw (no deps, needed only by gemm)
        cudaEventRecord(e0, 0);
        cudaStreamWaitEvent(s2, e0, 0);
        k_prepw<<<64, 256, 0, s2>>>(w2b, w1a, g1a, b2b);
        // s0: pc4, then fork knn to s1
        k_pc4<<<64, 256>>>(pcl);
        cudaEventRecord(e1, 0);
        cudaStreamWaitEvent(s1, e1, 0);
        k_knn<<<1024, 256, 0, s1>>>();
        // s0 leg: close (no weight dep) + prep + vtab
        k_close<<<1024, 256>>>(noise);
        k_prep<<<17, 256>>>(w2a, b2a, g2a, bt2a, b1a, g1a, bt1a, w1b);
        k_vtab<<<(B_*M_*HID_)/256, 256>>>(pcl);
        // join knn before assemble
        cudaEventRecord(e2, s1);
        cudaStreamWaitEvent(0, e2, 0);
        k_assemble<<<2048, 256>>>(pcl, noise, feature);
        // join prepw before gemm
        cudaEventRecord(e3, s2);
        cudaStreamWaitEvent(0, e3, 0);
        k_gemm<<<128, 256, GS_TOT>>>(b1b, out);
    } else {
        k_prepw<<<64, 256>>>(w2b, w1a, g1a, b2b);
        k_pc4<<<64, 256>>>(pcl);
        k_knn<<<1024, 256>>>();
        k_close<<<1024, 256>>>(noise);
        k_prep<<<17, 256>>>(w2a, b2a, g2a, bt2a, b1a, g1a, bt1a, w1b);
        k_vtab<<<(B_*M_*HID_)/256, 256>>>(pcl);
        k_assemble<<<2048, 256>>>(pcl, noise, feature);
        k_gemm<<<128, 256, GS_TOT>>>(b1b, out);
    }
}